// round 13
// baseline (speedup 1.0000x reference)
#include <cuda_runtime.h>
#include <cuda_fp16.h>
#include <math.h>
#include <cstdint>

// Problem: inputs (4, 8, 24, 24, 64) fp32 -> B=4, N=4608, C=64
// out = gamma * softmax(Q Q^T) Q + inputs,  Q = K = V = inputs.reshape(B,N,C)
//
// Flash attention, mma.sync.m16n8k16:
//   S  = Q K^T : fp16x3 (qh*kh + qh*kl + ql*kh)
//   O += P V   : fp16x1 (ph*vh)
// Warp tiling M=32 x N=64 (8 warps = 4 row-quarters x 2 k-halves), split-K
// combine at end. Each warp's 64 cols processed as TWO 32-col sub-tiles,
// software-pipelined S(A);SM(A);S(B);PV(A);SM(B);PV(B) so softmax MUFU/shfl
// overlaps sibling-sub-tile HMMAs inside one basic block.

#define BATCH   4
#define NTOK    4608
#define CDIM    64
#define BM      128
#define BN      128
#define NTILES  (NTOK / BN)   // 36

#define LDH 72                // half-tile row stride (64 + 8 pad)

#define QH_B    0
#define QL_B    18432
#define KB_H(buf) (36864 + (buf) * 36864)
#define KB_L(buf) (KB_H(buf) + 18432)
#define SMEM_DYN  (36864 + 2 * 36864)   // 110592

// epilogue aliases (Q tiles / KV buffer 0 dead by then)
#define OEP_LD  66
#define ML_B    36864

// ---------------- PTX helpers ----------------
__device__ __forceinline__ uint32_t smem_u32(const void* p) {
    uint32_t a;
    asm("{ .reg .u64 t; cvta.to.shared.u64 t, %1; cvt.u32.u64 %0, t; }" : "=r"(a) : "l"(p));
    return a;
}

#define LDSM_X4(r0, r1, r2, r3, a) \
    asm volatile("ldmatrix.sync.aligned.m8n8.x4.shared.b16 {%0,%1,%2,%3}, [%4];" \
        : "=r"(r0), "=r"(r1), "=r"(r2), "=r"(r3) : "r"(a))
#define LDSM_X4T(r0, r1, r2, r3, a) \
    asm volatile("ldmatrix.sync.aligned.m8n8.x4.trans.shared.b16 {%0,%1,%2,%3}, [%4];" \
        : "=r"(r0), "=r"(r1), "=r"(r2), "=r"(r3) : "r"(a))

#define MMA16816(c, a0, a1, a2, a3, b0, b1) \
    asm volatile("mma.sync.aligned.m16n8k16.row.col.f32.f16.f16.f32 " \
        "{%0,%1,%2,%3}, {%4,%5,%6,%7}, {%8,%9}, {%0,%1,%2,%3};" \
        : "+f"((c)[0]), "+f"((c)[1]), "+f"((c)[2]), "+f"((c)[3]) \
        : "r"(a0), "r"(a1), "r"(a2), "r"(a3), "r"(b0), "r"(b1))

__device__ __forceinline__ uint32_t h2u(half2 h) { return *(uint32_t*)&h; }

__device__ __forceinline__ void cvt_store(char* sm_h, char* sm_l, int r, int c, float4 v) {
    half2 h01 = __floats2half2_rn(v.x, v.y);
    half2 h23 = __floats2half2_rn(v.z, v.w);
    half2 l01 = __floats2half2_rn(v.x - __low2float(h01), v.y - __high2float(h01));
    half2 l23 = __floats2half2_rn(v.z - __low2float(h23), v.w - __high2float(h23));
    *(half2*)(sm_h + (r * LDH + c) * 2)     = h01;
    *(half2*)(sm_h + (r * LDH + c + 2) * 2) = h23;
    *(half2*)(sm_l + (r * LDH + c) * 2)     = l01;
    *(half2*)(sm_l + (r * LDH + c + 2) * 2) = l23;
}

// ---------------- fused attention ----------------
__global__ __launch_bounds__(256, 1)
void attn_mma_pipe2_kernel(const float* __restrict__ x,
                           const float* __restrict__ gamma_p,
                           float* __restrict__ out)
{
    extern __shared__ char sm[];
    const uint32_t smb = smem_u32(sm);

    const int tid  = threadIdx.x;
    const int w    = tid >> 5;
    const int lane = tid & 31;
    const int g    = lane >> 2;
    const int t4   = lane & 3;
    const int wm   = w & 3;        // row quarter: rows 32*wm .. +31
    const int wk   = w >> 2;       // k-half: S cols / V rows 64*wk .. +63

    const int b    = blockIdx.y;
    const int row0 = blockIdx.x * BM;
    const float* xb = x + (size_t)b * NTOK * CDIM;

    const int rload = tid >> 1;
    const int hload = (tid & 1) << 5;

    // ---- preamble: load Q tile + KV tile 0 (hi/lo split)
    {
        const float4* qsrc = (const float4*)(xb + (size_t)(row0 + rload) * CDIM + hload);
        const float4* ksrc = (const float4*)(xb + (size_t)rload * CDIM + hload);
        #pragma unroll
        for (int i = 0; i < 8; i++) {
            cvt_store(sm + QH_B, sm + QL_B, rload, hload + i * 4, qsrc[i]);
            cvt_store(sm + KB_H(0), sm + KB_L(0), rload, hload + i * 4, ksrc[i]);
        }
    }
    __syncthreads();

    // per-warp online softmax state
    float m[4], l[4];
    #pragma unroll
    for (int i = 0; i < 4; i++) { m[i] = -INFINITY; l[i] = 0.f; }
    float o[2][8][4];
    #pragma unroll
    for (int mt = 0; mt < 2; mt++)
        #pragma unroll
        for (int nt = 0; nt < 8; nt++)
            #pragma unroll
            for (int j = 0; j < 4; j++) o[mt][nt][j] = 0.f;

    const int l15 = lane & 15;
    const uint32_t kfrag_base = (uint32_t)((l15 & 7) * LDH + (l15 >> 3) * 8
                                           + (lane >> 4) * 8 * LDH) * 2;
    const uint32_t vfrag_base = (uint32_t)(l15 * LDH) * 2 + (uint32_t)(lane >> 4) * 16;
    const uint32_t qrow = (uint32_t)(wm * 32 + l15);
    const uint32_t qcol = (uint32_t)((lane >> 4) * 8);

    for (int t = 0; t < NTILES; t++) {
        const int cur = t & 1, nxt = cur ^ 1;
        const uint32_t kh = smb + KB_H(cur);
        const uint32_t kl = smb + KB_L(cur);

        // ---- S-GEMM for one 32-col sub-tile (h = 0/1 -> np 2h, 2h+1)
        auto s_half = [&](int h, float (&cc)[2][4][4]) {
            #pragma unroll
            for (int mt = 0; mt < 2; mt++)
                #pragma unroll
                for (int ntl = 0; ntl < 4; ntl++) {
                    cc[mt][ntl][0] = 0.f; cc[mt][ntl][1] = 0.f;
                    cc[mt][ntl][2] = 0.f; cc[mt][ntl][3] = 0.f;
                }
            #pragma unroll
            for (int kb = 0; kb < 4; kb++) {
                uint32_t q0h[4], q1h[4], q0l[4], q1l[4];
                {
                    uint32_t qo0 = (uint32_t)(qrow * LDH + kb * 16) * 2 + qcol * 2;
                    uint32_t qo1 = qo0 + (uint32_t)(16 * LDH) * 2;
                    LDSM_X4(q0h[0], q0h[1], q0h[2], q0h[3], smb + QH_B + qo0);
                    LDSM_X4(q1h[0], q1h[1], q1h[2], q1h[3], smb + QH_B + qo1);
                    LDSM_X4(q0l[0], q0l[1], q0l[2], q0l[3], smb + QL_B + qo0);
                    LDSM_X4(q1l[0], q1l[1], q1l[2], q1l[3], smb + QL_B + qo1);
                }
                #pragma unroll
                for (int npl = 0; npl < 2; npl++) {
                    const int np = h * 2 + npl;
                    uint32_t off = (uint32_t)((wk * 64 + np * 16) * LDH + kb * 16) * 2 + kfrag_base;
                    uint32_t bh0, bh1, bh2, bh3, bl0, bl1, bl2, bl3;
                    LDSM_X4(bh0, bh1, bh2, bh3, kh + off);
                    LDSM_X4(bl0, bl1, bl2, bl3, kl + off);
                    MMA16816(cc[0][2*npl],   q0h[0], q0h[1], q0h[2], q0h[3], bh0, bh1);
                    MMA16816(cc[0][2*npl+1], q0h[0], q0h[1], q0h[2], q0h[3], bh2, bh3);
                    MMA16816(cc[1][2*npl],   q1h[0], q1h[1], q1h[2], q1h[3], bh0, bh1);
                    MMA16816(cc[1][2*npl+1], q1h[0], q1h[1], q1h[2], q1h[3], bh2, bh3);
                    MMA16816(cc[0][2*npl],   q0h[0], q0h[1], q0h[2], q0h[3], bl0, bl1);
                    MMA16816(cc[0][2*npl+1], q0h[0], q0h[1], q0h[2], q0h[3], bl2, bl3);
                    MMA16816(cc[1][2*npl],   q1h[0], q1h[1], q1h[2], q1h[3], bl0, bl1);
                    MMA16816(cc[1][2*npl+1], q1h[0], q1h[1], q1h[2], q1h[3], bl2, bl3);
                    MMA16816(cc[0][2*npl],   q0l[0], q0l[1], q0l[2], q0l[3], bh0, bh1);
                    MMA16816(cc[0][2*npl+1], q0l[0], q0l[1], q0l[2], q0l[3], bh2, bh3);
                    MMA16816(cc[1][2*npl],   q1l[0], q1l[1], q1l[2], q1l[3], bh0, bh1);
                    MMA16816(cc[1][2*npl+1], q1l[0], q1l[1], q1l[2], q1l[3], bh2, bh3);
                }
            }
        };

        // ---- softmax over one sub-tile: update m/l, rescale o, pack P
        auto softmax_half = [&](float (&cc)[2][4][4], uint32_t (&pp)[2][2][4]) {
            float tm[4];
            #pragma unroll
            for (int i = 0; i < 4; i++) tm[i] = -INFINITY;
            #pragma unroll
            for (int mt = 0; mt < 2; mt++)
                #pragma unroll
                for (int ntl = 0; ntl < 4; ntl++) {
                    tm[2*mt]   = fmaxf(tm[2*mt],   fmaxf(cc[mt][ntl][0], cc[mt][ntl][1]));
                    tm[2*mt+1] = fmaxf(tm[2*mt+1], fmaxf(cc[mt][ntl][2], cc[mt][ntl][3]));
                }
            #pragma unroll
            for (int off = 1; off < 4; off <<= 1)
                #pragma unroll
                for (int i = 0; i < 4; i++)
                    tm[i] = fmaxf(tm[i], __shfl_xor_sync(0xffffffffu, tm[i], off));

            float nm[4], sc[4];
            #pragma unroll
            for (int i = 0; i < 4; i++) {
                nm[i] = fmaxf(m[i], tm[i]);
                sc[i] = __expf(m[i] - nm[i]);   // 0 on first sub-tile
                m[i]  = nm[i];
                l[i] *= sc[i];
            }
            #pragma unroll
            for (int mt = 0; mt < 2; mt++)
                #pragma unroll
                for (int nt = 0; nt < 8; nt++) {
                    o[mt][nt][0] *= sc[2*mt];   o[mt][nt][1] *= sc[2*mt];
                    o[mt][nt][2] *= sc[2*mt+1]; o[mt][nt][3] *= sc[2*mt+1];
                }

            #pragma unroll
            for (int kcl = 0; kcl < 2; kcl++) {
                #pragma unroll
                for (int mt = 0; mt < 2; mt++) {
                    const float* cA = cc[mt][2*kcl];
                    const float* cB = cc[mt][2*kcl+1];
                    float eA0 = __expf(cA[0] - nm[2*mt]);
                    float eA1 = __expf(cA[1] - nm[2*mt]);
                    float eA2 = __expf(cA[2] - nm[2*mt+1]);
                    float eA3 = __expf(cA[3] - nm[2*mt+1]);
                    float eB0 = __expf(cB[0] - nm[2*mt]);
                    float eB1 = __expf(cB[1] - nm[2*mt]);
                    float eB2 = __expf(cB[2] - nm[2*mt+1]);
                    float eB3 = __expf(cB[3] - nm[2*mt+1]);
                    l[2*mt]   += eA0 + eA1 + eB0 + eB1;
                    l[2*mt+1] += eA2 + eA3 + eB2 + eB3;
                    pp[kcl][mt][0] = h2u(__floats2half2_rn(eA0, eA1));
                    pp[kcl][mt][1] = h2u(__floats2half2_rn(eA2, eA3));
                    pp[kcl][mt][2] = h2u(__floats2half2_rn(eB0, eB1));
                    pp[kcl][mt][3] = h2u(__floats2half2_rn(eB2, eB3));
                }
            }
        };

        // ---- PV for one sub-tile (k-chunks 2h, 2h+1)
        auto pv_half = [&](int h, uint32_t (&pp)[2][2][4]) {
            #pragma unroll
            for (int kcl = 0; kcl < 2; kcl++) {
                const int kc = h * 2 + kcl;
                const uint32_t voffb = (uint32_t)((wk * 64 + kc * 16) * LDH) * 2 + vfrag_base;
                #pragma unroll
                for (int np = 0; np < 4; np++) {
                    uint32_t v0, v1, v2, v3;
                    LDSM_X4T(v0, v1, v2, v3, kh + voffb + (uint32_t)np * 32);
                    MMA16816(o[0][2*np],   pp[kcl][0][0], pp[kcl][0][1], pp[kcl][0][2], pp[kcl][0][3], v0, v1);
                    MMA16816(o[0][2*np+1], pp[kcl][0][0], pp[kcl][0][1], pp[kcl][0][2], pp[kcl][0][3], v2, v3);
                    MMA16816(o[1][2*np],   pp[kcl][1][0], pp[kcl][1][1], pp[kcl][1][2], pp[kcl][1][3], v0, v1);
                    MMA16816(o[1][2*np+1], pp[kcl][1][0], pp[kcl][1][1], pp[kcl][1][2], pp[kcl][1][3], v2, v3);
                }
            }
        };

        // ---- prefetch next KV tile (GMEM/L2 -> regs)
        float4 pre[8];
        if (t + 1 < NTILES) {
            const float4* src = (const float4*)(xb + (size_t)((t + 1) * BN + rload) * CDIM + hload);
            #pragma unroll
            for (int i = 0; i < 8; i++) pre[i] = src[i];
        }

        // ---- software-pipelined sub-tiles:
        //      S(A); SM(A); S(B); PV(A); SM(B); PV(B)
        float cA[2][4][4];
        uint32_t ppA[2][2][4];
        s_half(0, cA);
        softmax_half(cA, ppA);        // MUFU/shfl overlaps S(B) HMMAs

        float cB[2][4][4];
        s_half(1, cB);

        // store prefetched tile to the other buffer (frees pre regs)
        if (t + 1 < NTILES) {
            #pragma unroll
            for (int i = 0; i < 8; i++)
                cvt_store(sm + KB_H(nxt), sm + KB_L(nxt), rload, hload + i * 4, pre[i]);
        }

        uint32_t ppB[2][2][4];
        pv_half(0, ppA);
        softmax_half(cB, ppB);        // MUFU/shfl overlaps PV(A) HMMAs;
                                      // o-rescale ordered after PV(A) by dataflow
        pv_half(1, ppB);

        __syncthreads();
    }

    // ---- reduce l over the 4 lanes of each row group (warp-local)
    #pragma unroll
    for (int off = 1; off < 4; off <<= 1)
        #pragma unroll
        for (int i = 0; i < 4; i++)
            l[i] += __shfl_xor_sync(0xffffffffu, l[i], off);

    // ---- split-K combine through SMEM: k-half 1 publishes, k-half 0 merges
    float* smO = (float*)sm;               // [128][OEP_LD] fp32 partial O
    float* smM = (float*)(sm + ML_B);      // [128] partial m
    float* smL = smM + 128;                // [128] partial l

    if (wk == 1) {
        #pragma unroll
        for (int mt = 0; mt < 2; mt++) {
            const int r = wm * 32 + mt * 16 + g;
            if (t4 == 0) {
                smM[r]     = m[2*mt];   smL[r]     = l[2*mt];
                smM[r + 8] = m[2*mt+1]; smL[r + 8] = l[2*mt+1];
            }
            #pragma unroll
            for (int nt = 0; nt < 8; nt++) {
                const int col = nt * 8 + t4 * 2;
                smO[r * OEP_LD + col]           = o[mt][nt][0];
                smO[r * OEP_LD + col + 1]       = o[mt][nt][1];
                smO[(r + 8) * OEP_LD + col]     = o[mt][nt][2];
                smO[(r + 8) * OEP_LD + col + 1] = o[mt][nt][3];
            }
        }
    }
    __syncthreads();

    if (wk == 0) {
        const float gm = *gamma_p;
        #pragma unroll
        for (int mt = 0; mt < 2; mt++) {
            #pragma unroll
            for (int hh = 0; hh < 2; hh++) {
                const int rl = wm * 32 + mt * 16 + g + 8 * hh;
                const float mp = smM[rl], lp = smL[rl];
                const float mm = fmaxf(m[2*mt+hh], mp);
                const float s  = __expf(m[2*mt+hh] - mm);
                const float sp = __expf(mp - mm);
                const float inv = 1.f / (l[2*mt+hh] * s + lp * sp);
                const int rg = row0 + rl;
                #pragma unroll
                for (int nt = 0; nt < 8; nt++) {
                    const int col = nt * 8 + t4 * 2;
                    float v0 = o[mt][nt][2*hh]     * s + smO[rl * OEP_LD + col]     * sp;
                    float v1 = o[mt][nt][2*hh + 1] * s + smO[rl * OEP_LD + col + 1] * sp;
                    float2 xi = *(const float2*)(xb + (size_t)rg * CDIM + col);
                    float2 res;
                    res.x = fmaf(gm, v0 * inv, xi.x);
                    res.y = fmaf(gm, v1 * inv, xi.y);
                    *(float2*)(out + ((size_t)b * NTOK + rg) * CDIM + col) = res;
                }
            }
        }
    }
}

extern "C" void kernel_launch(void* const* d_in, const int* in_sizes, int n_in,
                              void* d_out, int out_size)
{
    const float* x     = (const float*)d_in[0];
    const float* gamma = (const float*)d_in[1];
    float* out = (float*)d_out;

    cudaFuncSetAttribute(attn_mma_pipe2_kernel,
                         cudaFuncAttributeMaxDynamicSharedMemorySize, SMEM_DYN);

    dim3 grid(NTOK / BM, BATCH);   // (36, 4) = 144 CTAs ~ one wave
    attn_mma_pipe2_kernel<<<grid, 256, SMEM_DYN>>>(x, gamma, out);
}

// round 14
// speedup vs baseline: 1.1127x; 1.1127x over previous
#include <cuda_runtime.h>
#include <cuda_fp16.h>
#include <math.h>
#include <cstdint>

// Problem: inputs (4, 8, 24, 24, 64) fp32 -> B=4, N=4608, C=64
// out = gamma * softmax(Q Q^T) Q + inputs,  Q = K = V = inputs.reshape(B,N,C)
//
// Flash attention, mma.sync.m16n8k16 (R12 structure):
//   S  = Q K^T : fp16x3 (qh*kh + qh*kl + ql*kh)
//   O += P V   : fp16x1 (ph*vh)
// fp32->fp16 hi/lo split PRECOMPUTED once into __device__ globals; KV tiles
// streamed into SMEM via cp.async (no per-tile cvt, no prefetch registers).
// Warp tiling M=32 x N=64 (8 warps = 4 row-quarters x 2 k-halves), split-K
// combine at end; one __syncthreads per tile.

#define BATCH   4
#define NTOK    4608
#define CDIM    64
#define BM      128
#define BN      128
#define NTILES  (NTOK / BN)   // 36

#define LDH 72                // half-tile row stride in halves (64 + 8 pad)
#define ROWB (LDH * 2)        // 144 bytes

#define QH_B    0
#define QL_B    18432
#define KB_H(buf) (36864 + (buf) * 36864)
#define KB_L(buf) (KB_H(buf) + 18432)
#define SMEM_DYN  (36864 + 2 * 36864)   // 110592

// epilogue aliases (Q tiles / KV buffer 0 dead by then)
#define OEP_LD  66
#define ML_B    36864

// Precomputed hi/lo fp16 copies of the input (scratch via __device__ globals)
__device__ uint16_t gXh[BATCH * NTOK * CDIM];
__device__ uint16_t gXl[BATCH * NTOK * CDIM];

// ---------------- PTX helpers ----------------
__device__ __forceinline__ uint32_t smem_u32(const void* p) {
    uint32_t a;
    asm("{ .reg .u64 t; cvta.to.shared.u64 t, %1; cvt.u32.u64 %0, t; }" : "=r"(a) : "l"(p));
    return a;
}

__device__ __forceinline__ void cp16(uint32_t dst, const void* src) {
    asm volatile("cp.async.cg.shared.global [%0], [%1], 16;"
                 :: "r"(dst), "l"(__cvta_generic_to_global(src)) : "memory");
}
#define CP_COMMIT() asm volatile("cp.async.commit_group;" ::: "memory")
#define CP_WAIT0()  asm volatile("cp.async.wait_group 0;"  ::: "memory")

#define LDSM_X4(r0, r1, r2, r3, a) \
    asm volatile("ldmatrix.sync.aligned.m8n8.x4.shared.b16 {%0,%1,%2,%3}, [%4];" \
        : "=r"(r0), "=r"(r1), "=r"(r2), "=r"(r3) : "r"(a))
#define LDSM_X4T(r0, r1, r2, r3, a) \
    asm volatile("ldmatrix.sync.aligned.m8n8.x4.trans.shared.b16 {%0,%1,%2,%3}, [%4];" \
        : "=r"(r0), "=r"(r1), "=r"(r2), "=r"(r3) : "r"(a))

#define MMA16816(c, a0, a1, a2, a3, b0, b1) \
    asm volatile("mma.sync.aligned.m16n8k16.row.col.f32.f16.f16.f32 " \
        "{%0,%1,%2,%3}, {%4,%5,%6,%7}, {%8,%9}, {%0,%1,%2,%3};" \
        : "+f"((c)[0]), "+f"((c)[1]), "+f"((c)[2]), "+f"((c)[3]) \
        : "r"(a0), "r"(a1), "r"(a2), "r"(a3), "r"(b0), "r"(b1))

__device__ __forceinline__ uint32_t h2u(half2 h) { return *(uint32_t*)&h; }

// ---------------- prepass: split fp32 -> fp16 hi/lo ----------------
__global__ void split_f32_f16_kernel(const float* __restrict__ x) {
    const int idx = blockIdx.x * blockDim.x + threadIdx.x;   // one float4 each
    float4 v = ((const float4*)x)[idx];
    half2 h01 = __floats2half2_rn(v.x, v.y);
    half2 h23 = __floats2half2_rn(v.z, v.w);
    half2 l01 = __floats2half2_rn(v.x - __low2float(h01), v.y - __high2float(h01));
    half2 l23 = __floats2half2_rn(v.z - __low2float(h23), v.w - __high2float(h23));
    uint32_t* ph = (uint32_t*)gXh;
    uint32_t* pl = (uint32_t*)gXl;
    ph[idx * 2]     = h2u(h01);
    ph[idx * 2 + 1] = h2u(h23);
    pl[idx * 2]     = h2u(l01);
    pl[idx * 2 + 1] = h2u(l23);
}

// ---------------- fused attention ----------------
__global__ __launch_bounds__(256, 1)
void attn_mma_cp_kernel(const float* __restrict__ x,
                        const float* __restrict__ gamma_p,
                        float* __restrict__ out)
{
    extern __shared__ char sm[];
    const uint32_t smb = smem_u32(sm);

    const int tid  = threadIdx.x;
    const int w    = tid >> 5;
    const int lane = tid & 31;
    const int g    = lane >> 2;
    const int t4   = lane & 3;
    const int wm   = w & 3;        // row quarter: rows 32*wm .. +31
    const int wk   = w >> 2;       // k-half: S cols / V rows 64*wk .. +63

    const int b    = blockIdx.y;
    const int row0 = blockIdx.x * BM;
    const float* xb = x + (size_t)b * NTOK * CDIM;
    const char* gxh = (const char*)gXh + (size_t)b * NTOK * 128;   // 128 B/row
    const char* gxl = (const char*)gXl + (size_t)b * NTOK * 128;

    const int rcp = tid >> 1;            // 0..127: row within tile
    const int ccp = (tid & 1) * 64;      // byte half within 128B row

    // issue cp.async copy of one 128-row tile (hi+lo) into SMEM buffer
    auto copy_tile = [&](int row_base, uint32_t dsth_base, uint32_t dstl_base) {
        const char* sh = gxh + (size_t)(row_base + rcp) * 128 + ccp;
        const char* sl = gxl + (size_t)(row_base + rcp) * 128 + ccp;
        uint32_t dh = dsth_base + (uint32_t)(rcp * ROWB + ccp);
        uint32_t dl = dstl_base + (uint32_t)(rcp * ROWB + ccp);
        #pragma unroll
        for (int i = 0; i < 4; i++) {
            cp16(dh + i * 16, sh + i * 16);
            cp16(dl + i * 16, sl + i * 16);
        }
    };

    // ---- preamble: Q tile + KV tile 0 via cp.async
    copy_tile(row0, smb + QH_B, smb + QL_B);
    copy_tile(0,    smb + KB_H(0), smb + KB_L(0));
    CP_COMMIT();
    CP_WAIT0();
    __syncthreads();

    // per-warp online softmax state
    float m[4], l[4];
    #pragma unroll
    for (int i = 0; i < 4; i++) { m[i] = -INFINITY; l[i] = 0.f; }
    float o[2][8][4];
    #pragma unroll
    for (int mt = 0; mt < 2; mt++)
        #pragma unroll
        for (int nt = 0; nt < 8; nt++)
            #pragma unroll
            for (int j = 0; j < 4; j++) o[mt][nt][j] = 0.f;

    const int l15 = lane & 15;
    const uint32_t kfrag_base = (uint32_t)((l15 & 7) * LDH + (l15 >> 3) * 8
                                           + (lane >> 4) * 8 * LDH) * 2;
    const uint32_t vfrag_base = (uint32_t)(l15 * LDH) * 2 + (uint32_t)(lane >> 4) * 16;
    const uint32_t qrow = (uint32_t)(wm * 32 + l15);
    const uint32_t qcol = (uint32_t)((lane >> 4) * 8);

    for (int t = 0; t < NTILES; t++) {
        const int cur = t & 1, nxt = cur ^ 1;
        const uint32_t kh = smb + KB_H(cur);
        const uint32_t kl = smb + KB_L(cur);

        // ---- stream next KV tile into the other buffer (async, overlaps all compute)
        if (t + 1 < NTILES) {
            copy_tile((t + 1) * BN, smb + KB_H(nxt), smb + KB_L(nxt));
            CP_COMMIT();
        }

        // ---- S = Q K^T over this warp's 64 cols (fp16x3)
        float c[2][8][4];
        #pragma unroll
        for (int mt = 0; mt < 2; mt++)
            #pragma unroll
            for (int nt = 0; nt < 8; nt++) {
                c[mt][nt][0] = 0.f; c[mt][nt][1] = 0.f;
                c[mt][nt][2] = 0.f; c[mt][nt][3] = 0.f;
            }

        #pragma unroll
        for (int kb = 0; kb < 4; kb++) {
            uint32_t q0h[4], q1h[4], q0l[4], q1l[4];
            {
                uint32_t qo0 = (uint32_t)(qrow * LDH + kb * 16) * 2 + qcol * 2;
                uint32_t qo1 = qo0 + (uint32_t)(16 * LDH) * 2;
                LDSM_X4(q0h[0], q0h[1], q0h[2], q0h[3], smb + QH_B + qo0);
                LDSM_X4(q1h[0], q1h[1], q1h[2], q1h[3], smb + QH_B + qo1);
                LDSM_X4(q0l[0], q0l[1], q0l[2], q0l[3], smb + QL_B + qo0);
                LDSM_X4(q1l[0], q1l[1], q1l[2], q1l[3], smb + QL_B + qo1);
            }
            #pragma unroll
            for (int np = 0; np < 4; np++) {
                uint32_t off = (uint32_t)((wk * 64 + np * 16) * LDH + kb * 16) * 2 + kfrag_base;
                uint32_t bh0, bh1, bh2, bh3, bl0, bl1, bl2, bl3;
                LDSM_X4(bh0, bh1, bh2, bh3, kh + off);
                LDSM_X4(bl0, bl1, bl2, bl3, kl + off);
                MMA16816(c[0][2*np],   q0h[0], q0h[1], q0h[2], q0h[3], bh0, bh1);
                MMA16816(c[0][2*np+1], q0h[0], q0h[1], q0h[2], q0h[3], bh2, bh3);
                MMA16816(c[1][2*np],   q1h[0], q1h[1], q1h[2], q1h[3], bh0, bh1);
                MMA16816(c[1][2*np+1], q1h[0], q1h[1], q1h[2], q1h[3], bh2, bh3);
                MMA16816(c[0][2*np],   q0h[0], q0h[1], q0h[2], q0h[3], bl0, bl1);
                MMA16816(c[0][2*np+1], q0h[0], q0h[1], q0h[2], q0h[3], bl2, bl3);
                MMA16816(c[1][2*np],   q1h[0], q1h[1], q1h[2], q1h[3], bl0, bl1);
                MMA16816(c[1][2*np+1], q1h[0], q1h[1], q1h[2], q1h[3], bl2, bl3);
                MMA16816(c[0][2*np],   q0l[0], q0l[1], q0l[2], q0l[3], bh0, bh1);
                MMA16816(c[0][2*np+1], q0l[0], q0l[1], q0l[2], q0l[3], bh2, bh3);
                MMA16816(c[1][2*np],   q1l[0], q1l[1], q1l[2], q1l[3], bh0, bh1);
                MMA16816(c[1][2*np+1], q1l[0], q1l[1], q1l[2], q1l[3], bh2, bh3);
            }
        }

        // ---- warp-local online softmax over this warp's 64 cols
        float tm[4];
        #pragma unroll
        for (int i = 0; i < 4; i++) tm[i] = -INFINITY;
        #pragma unroll
        for (int mt = 0; mt < 2; mt++)
            #pragma unroll
            for (int nt = 0; nt < 8; nt++) {
                tm[2*mt]   = fmaxf(tm[2*mt],   fmaxf(c[mt][nt][0], c[mt][nt][1]));
                tm[2*mt+1] = fmaxf(tm[2*mt+1], fmaxf(c[mt][nt][2], c[mt][nt][3]));
            }
        #pragma unroll
        for (int off = 1; off < 4; off <<= 1)
            #pragma unroll
            for (int i = 0; i < 4; i++)
                tm[i] = fmaxf(tm[i], __shfl_xor_sync(0xffffffffu, tm[i], off));

        float nm[4], sc[4];
        #pragma unroll
        for (int i = 0; i < 4; i++) {
            nm[i] = fmaxf(m[i], tm[i]);
            sc[i] = __expf(m[i] - nm[i]);
            m[i]  = nm[i];
            l[i] *= sc[i];
        }
        #pragma unroll
        for (int mt = 0; mt < 2; mt++)
            #pragma unroll
            for (int nt = 0; nt < 8; nt++) {
                o[mt][nt][0] *= sc[2*mt];   o[mt][nt][1] *= sc[2*mt];
                o[mt][nt][2] *= sc[2*mt+1]; o[mt][nt][3] *= sc[2*mt+1];
            }

        // ---- PV over this warp's k-half, per 16-wide k-chunk (fp16x1)
        #pragma unroll
        for (int kc = 0; kc < 4; kc++) {
            uint32_t pah[2][4];
            #pragma unroll
            for (int mt = 0; mt < 2; mt++) {
                const float* cA = c[mt][2*kc];
                const float* cB = c[mt][2*kc+1];
                float eA0 = __expf(cA[0] - nm[2*mt]);
                float eA1 = __expf(cA[1] - nm[2*mt]);
                float eA2 = __expf(cA[2] - nm[2*mt+1]);
                float eA3 = __expf(cA[3] - nm[2*mt+1]);
                float eB0 = __expf(cB[0] - nm[2*mt]);
                float eB1 = __expf(cB[1] - nm[2*mt]);
                float eB2 = __expf(cB[2] - nm[2*mt+1]);
                float eB3 = __expf(cB[3] - nm[2*mt+1]);
                l[2*mt]   += eA0 + eA1 + eB0 + eB1;
                l[2*mt+1] += eA2 + eA3 + eB2 + eB3;
                pah[mt][0] = h2u(__floats2half2_rn(eA0, eA1));
                pah[mt][1] = h2u(__floats2half2_rn(eA2, eA3));
                pah[mt][2] = h2u(__floats2half2_rn(eB0, eB1));
                pah[mt][3] = h2u(__floats2half2_rn(eB2, eB3));
            }

            const uint32_t voffb = (uint32_t)((wk * 64 + kc * 16) * LDH) * 2 + vfrag_base;
            #pragma unroll
            for (int np = 0; np < 4; np++) {
                uint32_t v0, v1, v2, v3;
                LDSM_X4T(v0, v1, v2, v3, kh + voffb + (uint32_t)np * 32);
                MMA16816(o[0][2*np],   pah[0][0], pah[0][1], pah[0][2], pah[0][3], v0, v1);
                MMA16816(o[0][2*np+1], pah[0][0], pah[0][1], pah[0][2], pah[0][3], v2, v3);
                MMA16816(o[1][2*np],   pah[1][0], pah[1][1], pah[1][2], pah[1][3], v0, v1);
                MMA16816(o[1][2*np+1], pah[1][0], pah[1][1], pah[1][2], pah[1][3], v2, v3);
            }
        }

        if (t + 1 < NTILES) CP_WAIT0();   // next buffer filled
        __syncthreads();
    }

    // ---- reduce l over the 4 lanes of each row group (warp-local)
    #pragma unroll
    for (int off = 1; off < 4; off <<= 1)
        #pragma unroll
        for (int i = 0; i < 4; i++)
            l[i] += __shfl_xor_sync(0xffffffffu, l[i], off);

    // ---- split-K combine through SMEM: k-half 1 publishes, k-half 0 merges
    float* smO = (float*)sm;               // [128][OEP_LD] fp32 partial O
    float* smM = (float*)(sm + ML_B);      // [128] partial m
    float* smL = smM + 128;                // [128] partial l

    if (wk == 1) {
        #pragma unroll
        for (int mt = 0; mt < 2; mt++) {
            const int r = wm * 32 + mt * 16 + g;
            if (t4 == 0) {
                smM[r]     = m[2*mt];   smL[r]     = l[2*mt];
                smM[r + 8] = m[2*mt+1]; smL[r + 8] = l[2*mt+1];
            }
            #pragma unroll
            for (int nt = 0; nt < 8; nt++) {
                const int col = nt * 8 + t4 * 2;
                smO[r * OEP_LD + col]           = o[mt][nt][0];
                smO[r * OEP_LD + col + 1]       = o[mt][nt][1];
                smO[(r + 8) * OEP_LD + col]     = o[mt][nt][2];
                smO[(r + 8) * OEP_LD + col + 1] = o[mt][nt][3];
            }
        }
    }
    __syncthreads();

    if (wk == 0) {
        const float gm = *gamma_p;
        #pragma unroll
        for (int mt = 0; mt < 2; mt++) {
            #pragma unroll
            for (int hh = 0; hh < 2; hh++) {
                const int rl = wm * 32 + mt * 16 + g + 8 * hh;
                const float mp = smM[rl], lp = smL[rl];
                const float mm = fmaxf(m[2*mt+hh], mp);
                const float s  = __expf(m[2*mt+hh] - mm);
                const float sp = __expf(mp - mm);
                const float inv = 1.f / (l[2*mt+hh] * s + lp * sp);
                const int rg = row0 + rl;
                #pragma unroll
                for (int nt = 0; nt < 8; nt++) {
                    const int col = nt * 8 + t4 * 2;
                    float v0 = o[mt][nt][2*hh]     * s + smO[rl * OEP_LD + col]     * sp;
                    float v1 = o[mt][nt][2*hh + 1] * s + smO[rl * OEP_LD + col + 1] * sp;
                    float2 xi = *(const float2*)(xb + (size_t)rg * CDIM + col);
                    float2 res;
                    res.x = fmaf(gm, v0 * inv, xi.x);
                    res.y = fmaf(gm, v1 * inv, xi.y);
                    *(float2*)(out + ((size_t)b * NTOK + rg) * CDIM + col) = res;
                }
            }
        }
    }
}

extern "C" void kernel_launch(void* const* d_in, const int* in_sizes, int n_in,
                              void* d_out, int out_size)
{
    const float* x     = (const float*)d_in[0];
    const float* gamma = (const float*)d_in[1];
    float* out = (float*)d_out;

    cudaFuncSetAttribute(attn_mma_cp_kernel,
                         cudaFuncAttributeMaxDynamicSharedMemorySize, SMEM_DYN);

    // prepass: one float4 per thread over the whole input
    const int nvec4 = BATCH * NTOK * CDIM / 4;        // 294912
    split_f32_f16_kernel<<<nvec4 / 256, 256>>>(x);

    dim3 grid(NTOK / BM, BATCH);   // (36, 4) = 144 CTAs ~ one wave
    attn_mma_cp_kernel<<<grid, 256, SMEM_DYN>>>(x, gamma, out);
}

// round 15
// speedup vs baseline: 1.1479x; 1.0316x over previous
#include <cuda_runtime.h>
#include <cuda_fp16.h>
#include <math.h>
#include <cstdint>

// Problem: inputs (4, 8, 24, 24, 64) fp32 -> B=4, N=4608, C=64
// out = gamma * softmax(Q Q^T) Q + inputs,  Q = K = V = inputs.reshape(B,N,C)
//
// Flash attention, mma.sync.m16n8k16 (R12 structure, bit-identical math):
//   S  = Q K^T : fp16x3 (qh*kh + qh*kl + ql*kh)
//   O += P V   : fp16x1 (ph*vh)
// fp32->fp16 hi/lo split precomputed ONCE into __device__ globals; per-tile
// KV movement is plain LDG.128 register prefetch + STS.128 (R12 schedule,
// no cvt, no async waits). Warp tiling M=32 x N=64 (4 row-quarters x 2
// k-halves), split-K combine at end, one __syncthreads per tile.

#define BATCH   4
#define NTOK    4608
#define CDIM    64
#define BM      128
#define BN      128
#define NTILES  (NTOK / BN)   // 36

#define LDH 72                // half-tile row stride in halves (64 + 8 pad)
#define ROWB (LDH * 2)        // 144 bytes

#define QH_B    0
#define QL_B    18432
#define KB_H(buf) (36864 + (buf) * 36864)
#define KB_L(buf) (KB_H(buf) + 18432)
#define SMEM_DYN  (36864 + 2 * 36864)   // 110592

// epilogue aliases (Q tiles / KV buffer 0 dead by then)
#define OEP_LD  66
#define ML_B    36864

// Precomputed hi/lo fp16 copies of the input (scratch via __device__ globals)
__device__ uint16_t gXh[BATCH * NTOK * CDIM];
__device__ uint16_t gXl[BATCH * NTOK * CDIM];

// ---------------- PTX helpers ----------------
__device__ __forceinline__ uint32_t smem_u32(const void* p) {
    uint32_t a;
    asm("{ .reg .u64 t; cvta.to.shared.u64 t, %1; cvt.u32.u64 %0, t; }" : "=r"(a) : "l"(p));
    return a;
}

#define LDSM_X4(r0, r1, r2, r3, a) \
    asm volatile("ldmatrix.sync.aligned.m8n8.x4.shared.b16 {%0,%1,%2,%3}, [%4];" \
        : "=r"(r0), "=r"(r1), "=r"(r2), "=r"(r3) : "r"(a))
#define LDSM_X4T(r0, r1, r2, r3, a) \
    asm volatile("ldmatrix.sync.aligned.m8n8.x4.trans.shared.b16 {%0,%1,%2,%3}, [%4];" \
        : "=r"(r0), "=r"(r1), "=r"(r2), "=r"(r3) : "r"(a))

#define MMA16816(c, a0, a1, a2, a3, b0, b1) \
    asm volatile("mma.sync.aligned.m16n8k16.row.col.f32.f16.f16.f32 " \
        "{%0,%1,%2,%3}, {%4,%5,%6,%7}, {%8,%9}, {%0,%1,%2,%3};" \
        : "+f"((c)[0]), "+f"((c)[1]), "+f"((c)[2]), "+f"((c)[3]) \
        : "r"(a0), "r"(a1), "r"(a2), "r"(a3), "r"(b0), "r"(b1))

__device__ __forceinline__ uint32_t h2u(half2 h) { return *(uint32_t*)&h; }

// ---------------- prepass: split fp32 -> fp16 hi/lo ----------------
__global__ void split_f32_f16_kernel(const float* __restrict__ x) {
    const int idx = blockIdx.x * blockDim.x + threadIdx.x;   // one float4 each
    float4 v = ((const float4*)x)[idx];
    half2 h01 = __floats2half2_rn(v.x, v.y);
    half2 h23 = __floats2half2_rn(v.z, v.w);
    half2 l01 = __floats2half2_rn(v.x - __low2float(h01), v.y - __high2float(h01));
    half2 l23 = __floats2half2_rn(v.z - __low2float(h23), v.w - __high2float(h23));
    uint32_t* ph = (uint32_t*)gXh;
    uint32_t* pl = (uint32_t*)gXl;
    ph[idx * 2]     = h2u(h01);
    ph[idx * 2 + 1] = h2u(h23);
    pl[idx * 2]     = h2u(l01);
    pl[idx * 2 + 1] = h2u(l23);
}

// ---------------- fused attention ----------------
__global__ __launch_bounds__(256, 1)
void attn_mma_pre_kernel(const float* __restrict__ x,
                         const float* __restrict__ gamma_p,
                         float* __restrict__ out)
{
    extern __shared__ char sm[];
    const uint32_t smb = smem_u32(sm);

    const int tid  = threadIdx.x;
    const int w    = tid >> 5;
    const int lane = tid & 31;
    const int g    = lane >> 2;
    const int t4   = lane & 3;
    const int wm   = w & 3;        // row quarter: rows 32*wm .. +31
    const int wk   = w >> 2;       // k-half: S cols / V rows 64*wk .. +63

    const int b    = blockIdx.y;
    const int row0 = blockIdx.x * BM;
    const float* xb = x + (size_t)b * NTOK * CDIM;
    const char* gxh = (const char*)gXh + (size_t)b * NTOK * 128;   // 128 B/row
    const char* gxl = (const char*)gXl + (size_t)b * NTOK * 128;

    const int rcp = tid >> 1;            // 0..127: row within tile
    const int ccp = (tid & 1) * 64;      // byte half within 128B row

    // synchronous copy of one 128-row tile (hi+lo) into an SMEM buffer
    auto copy_tile_sync = [&](int row_base, uint32_t dsth, uint32_t dstl) {
        const uint4* sh = (const uint4*)(gxh + (size_t)(row_base + rcp) * 128 + ccp);
        const uint4* sl = (const uint4*)(gxl + (size_t)(row_base + rcp) * 128 + ccp);
        const uint32_t db = (uint32_t)(rcp * ROWB + ccp);
        #pragma unroll
        for (int i = 0; i < 4; i++) {
            *(uint4*)(sm + dsth - smb + db + i * 16) = sh[i];
            *(uint4*)(sm + dstl - smb + db + i * 16) = sl[i];
        }
    };

    // ---- preamble: Q tile + KV tile 0
    copy_tile_sync(row0, smb + QH_B, smb + QL_B);
    copy_tile_sync(0,    smb + KB_H(0), smb + KB_L(0));
    __syncthreads();

    // per-warp online softmax state
    float m[4], l[4];
    #pragma unroll
    for (int i = 0; i < 4; i++) { m[i] = -INFINITY; l[i] = 0.f; }
    float o[2][8][4];
    #pragma unroll
    for (int mt = 0; mt < 2; mt++)
        #pragma unroll
        for (int nt = 0; nt < 8; nt++)
            #pragma unroll
            for (int j = 0; j < 4; j++) o[mt][nt][j] = 0.f;

    const int l15 = lane & 15;
    const uint32_t kfrag_base = (uint32_t)((l15 & 7) * LDH + (l15 >> 3) * 8
                                           + (lane >> 4) * 8 * LDH) * 2;
    const uint32_t vfrag_base = (uint32_t)(l15 * LDH) * 2 + (uint32_t)(lane >> 4) * 16;
    const uint32_t qrow = (uint32_t)(wm * 32 + l15);
    const uint32_t qcol = (uint32_t)((lane >> 4) * 8);

    for (int t = 0; t < NTILES; t++) {
        const int cur = t & 1, nxt = cur ^ 1;
        const uint32_t kh = smb + KB_H(cur);
        const uint32_t kl = smb + KB_L(cur);

        // ---- prefetch next KV tile (GMEM/L2 -> regs), R12 schedule
        uint4 preh[4], prel[4];
        if (t + 1 < NTILES) {
            const uint4* sh = (const uint4*)(gxh + (size_t)((t + 1) * BN + rcp) * 128 + ccp);
            const uint4* sl = (const uint4*)(gxl + (size_t)((t + 1) * BN + rcp) * 128 + ccp);
            #pragma unroll
            for (int i = 0; i < 4; i++) { preh[i] = sh[i]; prel[i] = sl[i]; }
        }

        // ---- S = Q K^T over this warp's 64 cols (fp16x3)
        float c[2][8][4];
        #pragma unroll
        for (int mt = 0; mt < 2; mt++)
            #pragma unroll
            for (int nt = 0; nt < 8; nt++) {
                c[mt][nt][0] = 0.f; c[mt][nt][1] = 0.f;
                c[mt][nt][2] = 0.f; c[mt][nt][3] = 0.f;
            }

        #pragma unroll
        for (int kb = 0; kb < 4; kb++) {
            uint32_t q0h[4], q1h[4], q0l[4], q1l[4];
            {
                uint32_t qo0 = (uint32_t)(qrow * LDH + kb * 16) * 2 + qcol * 2;
                uint32_t qo1 = qo0 + (uint32_t)(16 * LDH) * 2;
                LDSM_X4(q0h[0], q0h[1], q0h[2], q0h[3], smb + QH_B + qo0);
                LDSM_X4(q1h[0], q1h[1], q1h[2], q1h[3], smb + QH_B + qo1);
                LDSM_X4(q0l[0], q0l[1], q0l[2], q0l[3], smb + QL_B + qo0);
                LDSM_X4(q1l[0], q1l[1], q1l[2], q1l[3], smb + QL_B + qo1);
            }
            #pragma unroll
            for (int np = 0; np < 4; np++) {
                uint32_t off = (uint32_t)((wk * 64 + np * 16) * LDH + kb * 16) * 2 + kfrag_base;
                uint32_t bh0, bh1, bh2, bh3, bl0, bl1, bl2, bl3;
                LDSM_X4(bh0, bh1, bh2, bh3, kh + off);
                LDSM_X4(bl0, bl1, bl2, bl3, kl + off);
                MMA16816(c[0][2*np],   q0h[0], q0h[1], q0h[2], q0h[3], bh0, bh1);
                MMA16816(c[0][2*np+1], q0h[0], q0h[1], q0h[2], q0h[3], bh2, bh3);
                MMA16816(c[1][2*np],   q1h[0], q1h[1], q1h[2], q1h[3], bh0, bh1);
                MMA16816(c[1][2*np+1], q1h[0], q1h[1], q1h[2], q1h[3], bh2, bh3);
                MMA16816(c[0][2*np],   q0h[0], q0h[1], q0h[2], q0h[3], bl0, bl1);
                MMA16816(c[0][2*np+1], q0h[0], q0h[1], q0h[2], q0h[3], bl2, bl3);
                MMA16816(c[1][2*np],   q1h[0], q1h[1], q1h[2], q1h[3], bl0, bl1);
                MMA16816(c[1][2*np+1], q1h[0], q1h[1], q1h[2], q1h[3], bl2, bl3);
                MMA16816(c[0][2*np],   q0l[0], q0l[1], q0l[2], q0l[3], bh0, bh1);
                MMA16816(c[0][2*np+1], q0l[0], q0l[1], q0l[2], q0l[3], bh2, bh3);
                MMA16816(c[1][2*np],   q1l[0], q1l[1], q1l[2], q1l[3], bh0, bh1);
                MMA16816(c[1][2*np+1], q1l[0], q1l[1], q1l[2], q1l[3], bh2, bh3);
            }
        }

        // ---- store prefetched tile to the other buffer (R12 placement)
        if (t + 1 < NTILES) {
            const uint32_t db = (uint32_t)(rcp * ROWB + ccp);
            #pragma unroll
            for (int i = 0; i < 4; i++) {
                *(uint4*)(sm + KB_H(nxt) + db + i * 16) = preh[i];
                *(uint4*)(sm + KB_L(nxt) + db + i * 16) = prel[i];
            }
        }

        // ---- warp-local online softmax over this warp's 64 cols
        float tm[4];
        #pragma unroll
        for (int i = 0; i < 4; i++) tm[i] = -INFINITY;
        #pragma unroll
        for (int mt = 0; mt < 2; mt++)
            #pragma unroll
            for (int nt = 0; nt < 8; nt++) {
                tm[2*mt]   = fmaxf(tm[2*mt],   fmaxf(c[mt][nt][0], c[mt][nt][1]));
                tm[2*mt+1] = fmaxf(tm[2*mt+1], fmaxf(c[mt][nt][2], c[mt][nt][3]));
            }
        #pragma unroll
        for (int off = 1; off < 4; off <<= 1)
            #pragma unroll
            for (int i = 0; i < 4; i++)
                tm[i] = fmaxf(tm[i], __shfl_xor_sync(0xffffffffu, tm[i], off));

        float nm[4], sc[4];
        #pragma unroll
        for (int i = 0; i < 4; i++) {
            nm[i] = fmaxf(m[i], tm[i]);
            sc[i] = __expf(m[i] - nm[i]);
            m[i]  = nm[i];
            l[i] *= sc[i];
        }
        #pragma unroll
        for (int mt = 0; mt < 2; mt++)
            #pragma unroll
            for (int nt = 0; nt < 8; nt++) {
                o[mt][nt][0] *= sc[2*mt];   o[mt][nt][1] *= sc[2*mt];
                o[mt][nt][2] *= sc[2*mt+1]; o[mt][nt][3] *= sc[2*mt+1];
            }

        // ---- PV over this warp's k-half, per 16-wide k-chunk (fp16x1)
        #pragma unroll
        for (int kc = 0; kc < 4; kc++) {
            uint32_t pah[2][4];
            #pragma unroll
            for (int mt = 0; mt < 2; mt++) {
                const float* cA = c[mt][2*kc];
                const float* cB = c[mt][2*kc+1];
                float eA0 = __expf(cA[0] - nm[2*mt]);
                float eA1 = __expf(cA[1] - nm[2*mt]);
                float eA2 = __expf(cA[2] - nm[2*mt+1]);
                float eA3 = __expf(cA[3] - nm[2*mt+1]);
                float eB0 = __expf(cB[0] - nm[2*mt]);
                float eB1 = __expf(cB[1] - nm[2*mt]);
                float eB2 = __expf(cB[2] - nm[2*mt+1]);
                float eB3 = __expf(cB[3] - nm[2*mt+1]);
                l[2*mt]   += eA0 + eA1 + eB0 + eB1;
                l[2*mt+1] += eA2 + eA3 + eB2 + eB3;
                pah[mt][0] = h2u(__floats2half2_rn(eA0, eA1));
                pah[mt][1] = h2u(__floats2half2_rn(eA2, eA3));
                pah[mt][2] = h2u(__floats2half2_rn(eB0, eB1));
                pah[mt][3] = h2u(__floats2half2_rn(eB2, eB3));
            }

            const uint32_t voffb = (uint32_t)((wk * 64 + kc * 16) * LDH) * 2 + vfrag_base;
            #pragma unroll
            for (int np = 0; np < 4; np++) {
                uint32_t v0, v1, v2, v3;
                LDSM_X4T(v0, v1, v2, v3, kh + voffb + (uint32_t)np * 32);
                MMA16816(o[0][2*np],   pah[0][0], pah[0][1], pah[0][2], pah[0][3], v0, v1);
                MMA16816(o[0][2*np+1], pah[0][0], pah[0][1], pah[0][2], pah[0][3], v2, v3);
                MMA16816(o[1][2*np],   pah[1][0], pah[1][1], pah[1][2], pah[1][3], v0, v1);
                MMA16816(o[1][2*np+1], pah[1][0], pah[1][1], pah[1][2], pah[1][3], v2, v3);
            }
        }

        __syncthreads();
    }

    // ---- reduce l over the 4 lanes of each row group (warp-local)
    #pragma unroll
    for (int off = 1; off < 4; off <<= 1)
        #pragma unroll
        for (int i = 0; i < 4; i++)
            l[i] += __shfl_xor_sync(0xffffffffu, l[i], off);

    // ---- split-K combine through SMEM: k-half 1 publishes, k-half 0 merges
    float* smO = (float*)sm;               // [128][OEP_LD] fp32 partial O
    float* smM = (float*)(sm + ML_B);      // [128] partial m
    float* smL = smM + 128;                // [128] partial l

    if (wk == 1) {
        #pragma unroll
        for (int mt = 0; mt < 2; mt++) {
            const int r = wm * 32 + mt * 16 + g;
            if (t4 == 0) {
                smM[r]     = m[2*mt];   smL[r]     = l[2*mt];
                smM[r + 8] = m[2*mt+1]; smL[r + 8] = l[2*mt+1];
            }
            #pragma unroll
            for (int nt = 0; nt < 8; nt++) {
                const int col = nt * 8 + t4 * 2;
                smO[r * OEP_LD + col]           = o[mt][nt][0];
                smO[r * OEP_LD + col + 1]       = o[mt][nt][1];
                smO[(r + 8) * OEP_LD + col]     = o[mt][nt][2];
                smO[(r + 8) * OEP_LD + col + 1] = o[mt][nt][3];
            }
        }
    }
    __syncthreads();

    if (wk == 0) {
        const float gm = *gamma_p;
        #pragma unroll
        for (int mt = 0; mt < 2; mt++) {
            #pragma unroll
            for (int hh = 0; hh < 2; hh++) {
                const int rl = wm * 32 + mt * 16 + g + 8 * hh;
                const float mp = smM[rl], lp = smL[rl];
                const float mm = fmaxf(m[2*mt+hh], mp);
                const float s  = __expf(m[2*mt+hh] - mm);
                const float sp = __expf(mp - mm);
                const float inv = 1.f / (l[2*mt+hh] * s + lp * sp);
                const int rg = row0 + rl;
                #pragma unroll
                for (int nt = 0; nt < 8; nt++) {
                    const int col = nt * 8 + t4 * 2;
                    float v0 = o[mt][nt][2*hh]     * s + smO[rl * OEP_LD + col]     * sp;
                    float v1 = o[mt][nt][2*hh + 1] * s + smO[rl * OEP_LD + col + 1] * sp;
                    float2 xi = *(const float2*)(xb + (size_t)rg * CDIM + col);
                    float2 res;
                    res.x = fmaf(gm, v0 * inv, xi.x);
                    res.y = fmaf(gm, v1 * inv, xi.y);
                    *(float2*)(out + ((size_t)b * NTOK + rg) * CDIM + col) = res;
                }
            }
        }
    }
}

extern "C" void kernel_launch(void* const* d_in, const int* in_sizes, int n_in,
                              void* d_out, int out_size)
{
    const float* x     = (const float*)d_in[0];
    const float* gamma = (const float*)d_in[1];
    float* out = (float*)d_out;

    cudaFuncSetAttribute(attn_mma_pre_kernel,
                         cudaFuncAttributeMaxDynamicSharedMemorySize, SMEM_DYN);

    // prepass: one float4 per thread over the whole input
    const int nvec4 = BATCH * NTOK * CDIM / 4;        // 294912
    split_f32_f16_kernel<<<nvec4 / 256, 256>>>(x);

    dim3 grid(NTOK / BM, BATCH);   // (36, 4) = 144 CTAs ~ one wave
    attn_mma_pre_kernel<<<grid, 256, SMEM_DYN>>>(x, gamma, out);
}